// round 5
// baseline (speedup 1.0000x reference)
#include <cuda_runtime.h>
#include <math.h>

#define N_NODES 100000
#define IN_DIM 64
#define HALF 32

// ---------------- scratch (device globals: allocation-free) ----------------
__device__ float4 g_aggP[N_NODES * 16];   // 100k x 64 floats
__device__ float4 g_aggN[N_NODES * 16];
__device__ float4 g_z[N_NODES * 16];      // tanh output of layer 1
__device__ float  g_cntP[N_NODES];
__device__ float  g_cntN[N_NODES];

// ---------------- zero kernels ----------------
__global__ void zero_layer1() {
    int i = blockIdx.x * blockDim.x + threadIdx.x;
    float4 z4 = make_float4(0.f, 0.f, 0.f, 0.f);
    if (i < N_NODES * 16) { g_aggP[i] = z4; g_aggN[i] = z4; }
    if (i < N_NODES)      { g_cntP[i] = 0.f; g_cntN[i] = 0.f; }
}
__global__ void zero_layer2() {
    int i = blockIdx.x * blockDim.x + threadIdx.x;
    float4 z4 = make_float4(0.f, 0.f, 0.f, 0.f);
    if (i < N_NODES * 16) { g_aggP[i] = z4; g_aggN[i] = z4; }
}

// ---------------- edge aggregation ----------------
__global__ void __launch_bounds__(256)
agg_kernel(const float4* __restrict__ xfeat,
           const int* __restrict__ src, const int* __restrict__ dst,
           int nEdges, int featSel, int outSel, int doCnt)
{
    int t = blockIdx.x * blockDim.x + threadIdx.x;
    if (t >= nEdges * 16) return;
    int e = t >> 4;
    int c = t & 15;
    int s = __ldg(src + e);
    int d = __ldg(dst + e);
    const float4* feat = featSel ? (const float4*)g_z : xfeat;
    float4* out = outSel ? g_aggN : g_aggP;
    float4 v = __ldg(feat + s * 16 + c);
    float4* p = out + d * 16 + c;
    asm volatile("red.global.add.v4.f32 [%0], {%1,%2,%3,%4};"
                 :: "l"(p), "f"(v.x), "f"(v.y), "f"(v.z), "f"(v.w) : "memory");
    if (doCnt && c == 0) {
        float* cnt = outSel ? g_cntN : g_cntP;
        atomicAdd(cnt + d, 1.0f);
    }
}

// ---------------- layer 1 (register-tiled GEMM, 2 nodes x 4 outputs / thread) ----------------
// branch0 (j 0..31):  tanh( [aggP*invP, x] @ w1b + b1b )
// branch1 (j 32..63): tanh( [aggN*invN, x] @ w1u + b1u )
// outputs j = branch*32 + jb + 8*o
#define RS1 132
__global__ void __launch_bounds__(256)
linear1_v4(const float* __restrict__ x,
           const float* __restrict__ w1b, const float* __restrict__ b1b,
           const float* __restrict__ w1u, const float* __restrict__ b1u)
{
    __shared__ float sW[2][32][RS1];   // transposed: sW[branch][j][k]
    __shared__ float sB[64];
    int tid = threadIdx.x;
    for (int i = tid; i < 128 * 32; i += 256) {
        int k = i >> 5, j = i & 31;
        sW[0][j][k] = w1b[i];
        sW[1][j][k] = w1u[i];
    }
    if (tid < 32) { sB[tid] = b1b[tid]; sB[tid + 32] = b1u[tid]; }
    __syncthreads();

    int jg = tid & 15, ng = tid >> 4;      // 16 node-groups of 2 nodes
    int branch = jg >> 3, jb = jg & 7;
    const float* agg = branch ? (const float*)g_aggN : (const float*)g_aggP;
    const float* cnt = branch ? g_cntN : g_cntP;
    float* zout = (float*)g_z;

    int nbase = blockIdx.x * 32 + ng * 2;
    int nidx[2];
    float inv[2];
    #pragma unroll
    for (int ni = 0; ni < 2; ni++) {
        int n = nbase + ni; if (n > N_NODES - 1) n = N_NODES - 1;
        nidx[ni] = n;
        inv[ni] = 1.0f / fmaxf(cnt[n], 1.0f);
    }

    float acc[2][4], tmp[2][4];
    #pragma unroll
    for (int ni = 0; ni < 2; ni++)
        #pragma unroll
        for (int o = 0; o < 4; o++) {
            acc[ni][o] = sB[branch * 32 + jb + 8 * o];
            tmp[ni][o] = 0.f;
        }

    // region A: aggregated features (k = 0..63) -> tmp (scaled at the end)
    #pragma unroll 4
    for (int ch = 0; ch < 16; ch++) {
        float4 v[2], w[4];
        #pragma unroll
        for (int ni = 0; ni < 2; ni++)
            v[ni] = *(const float4*)(agg + nidx[ni] * 64 + ch * 4);
        #pragma unroll
        for (int o = 0; o < 4; o++)
            w[o] = *(const float4*)&sW[branch][jb + 8 * o][ch * 4];
        #pragma unroll
        for (int ni = 0; ni < 2; ni++)
            #pragma unroll
            for (int o = 0; o < 4; o++) {
                tmp[ni][o] = fmaf(v[ni].x, w[o].x, tmp[ni][o]);
                tmp[ni][o] = fmaf(v[ni].y, w[o].y, tmp[ni][o]);
                tmp[ni][o] = fmaf(v[ni].z, w[o].z, tmp[ni][o]);
                tmp[ni][o] = fmaf(v[ni].w, w[o].w, tmp[ni][o]);
            }
    }
    // region B: self features x (k = 64..127) -> acc
    #pragma unroll 4
    for (int ch = 0; ch < 16; ch++) {
        float4 v[2], w[4];
        #pragma unroll
        for (int ni = 0; ni < 2; ni++)
            v[ni] = *(const float4*)(x + nidx[ni] * 64 + ch * 4);
        #pragma unroll
        for (int o = 0; o < 4; o++)
            w[o] = *(const float4*)&sW[branch][jb + 8 * o][64 + ch * 4];
        #pragma unroll
        for (int ni = 0; ni < 2; ni++)
            #pragma unroll
            for (int o = 0; o < 4; o++) {
                acc[ni][o] = fmaf(v[ni].x, w[o].x, acc[ni][o]);
                acc[ni][o] = fmaf(v[ni].y, w[o].y, acc[ni][o]);
                acc[ni][o] = fmaf(v[ni].z, w[o].z, acc[ni][o]);
                acc[ni][o] = fmaf(v[ni].w, w[o].w, acc[ni][o]);
            }
    }

    #pragma unroll
    for (int ni = 0; ni < 2; ni++) {
        int n = nbase + ni;
        if (n < N_NODES) {
            #pragma unroll
            for (int o = 0; o < 4; o++) {
                float r = tanhf(acc[ni][o] + tmp[ni][o] * inv[ni]);
                zout[n * 64 + branch * 32 + jb + 8 * o] = r;
            }
        }
    }
}

// ---------------- layer 2 (register-tiled GEMM, 2 nodes x 4 outputs / thread) ----------------
// branch0: in = [aggP[0:32]*invP,  aggN[32:64]*invN, z[0:32] ] @ w2b + b2b
// branch1: in = [aggP[32:64]*invP, aggN[0:32]*invN,  z[32:64]] @ w2u + b2u
#define RS2 100
__global__ void __launch_bounds__(256)
linear2_v4(const float* __restrict__ w2b, const float* __restrict__ b2b,
           const float* __restrict__ w2u, const float* __restrict__ b2u,
           float* __restrict__ out)
{
    __shared__ float sW[2][32][RS2];
    __shared__ float sB[64];
    int tid = threadIdx.x;
    for (int i = tid; i < 96 * 32; i += 256) {
        int k = i >> 5, j = i & 31;
        sW[0][j][k] = w2b[i];
        sW[1][j][k] = w2u[i];
    }
    if (tid < 32) { sB[tid] = b2b[tid]; sB[tid + 32] = b2u[tid]; }
    __syncthreads();

    int jg = tid & 15, ng = tid >> 4;
    int branch = jg >> 3, jb = jg & 7;
    const float* aggP = (const float*)g_aggP;
    const float* aggN = (const float*)g_aggN;
    const float* z = (const float*)g_z;

    int offA = branch * 32;
    int offB = (1 - branch) * 32;
    int offC = branch * 32;

    int nbase = blockIdx.x * 32 + ng * 2;
    int nidx[2];
    float invP[2], invN[2];
    #pragma unroll
    for (int ni = 0; ni < 2; ni++) {
        int n = nbase + ni; if (n > N_NODES - 1) n = N_NODES - 1;
        nidx[ni] = n;
        invP[ni] = 1.0f / fmaxf(g_cntP[n], 1.0f);
        invN[ni] = 1.0f / fmaxf(g_cntN[n], 1.0f);
    }

    float acc[2][4], tmp[2][4];
    #pragma unroll
    for (int ni = 0; ni < 2; ni++)
        #pragma unroll
        for (int o = 0; o < 4; o++) {
            acc[ni][o] = sB[branch * 32 + jb + 8 * o];
            tmp[ni][o] = 0.f;
        }

    // region A: aggP slice (k = 0..31) -> tmp, fold with invP
    #pragma unroll
    for (int ch = 0; ch < 8; ch++) {
        float4 v[2], w[4];
        #pragma unroll
        for (int ni = 0; ni < 2; ni++)
            v[ni] = *(const float4*)(aggP + nidx[ni] * 64 + offA + ch * 4);
        #pragma unroll
        for (int o = 0; o < 4; o++)
            w[o] = *(const float4*)&sW[branch][jb + 8 * o][ch * 4];
        #pragma unroll
        for (int ni = 0; ni < 2; ni++)
            #pragma unroll
            for (int o = 0; o < 4; o++) {
                tmp[ni][o] = fmaf(v[ni].x, w[o].x, tmp[ni][o]);
                tmp[ni][o] = fmaf(v[ni].y, w[o].y, tmp[ni][o]);
                tmp[ni][o] = fmaf(v[ni].z, w[o].z, tmp[ni][o]);
                tmp[ni][o] = fmaf(v[ni].w, w[o].w, tmp[ni][o]);
            }
    }
    #pragma unroll
    for (int ni = 0; ni < 2; ni++)
        #pragma unroll
        for (int o = 0; o < 4; o++) {
            acc[ni][o] = fmaf(tmp[ni][o], invP[ni], acc[ni][o]);
            tmp[ni][o] = 0.f;
        }

    // region B: aggN slice (k = 32..63) -> tmp, fold with invN
    #pragma unroll
    for (int ch = 0; ch < 8; ch++) {
        float4 v[2], w[4];
        #pragma unroll
        for (int ni = 0; ni < 2; ni++)
            v[ni] = *(const float4*)(aggN + nidx[ni] * 64 + offB + ch * 4);
        #pragma unroll
        for (int o = 0; o < 4; o++)
            w[o] = *(const float4*)&sW[branch][jb + 8 * o][32 + ch * 4];
        #pragma unroll
        for (int ni = 0; ni < 2; ni++)
            #pragma unroll
            for (int o = 0; o < 4; o++) {
                tmp[ni][o] = fmaf(v[ni].x, w[o].x, tmp[ni][o]);
                tmp[ni][o] = fmaf(v[ni].y, w[o].y, tmp[ni][o]);
                tmp[ni][o] = fmaf(v[ni].z, w[o].z, tmp[ni][o]);
                tmp[ni][o] = fmaf(v[ni].w, w[o].w, tmp[ni][o]);
            }
    }
    #pragma unroll
    for (int ni = 0; ni < 2; ni++)
        #pragma unroll
        for (int o = 0; o < 4; o++)
            acc[ni][o] = fmaf(tmp[ni][o], invN[ni], acc[ni][o]);

    // region C: z slice (k = 64..95) -> acc directly
    #pragma unroll
    for (int ch = 0; ch < 8; ch++) {
        float4 v[2], w[4];
        #pragma unroll
        for (int ni = 0; ni < 2; ni++)
            v[ni] = *(const float4*)(z + nidx[ni] * 64 + offC + ch * 4);
        #pragma unroll
        for (int o = 0; o < 4; o++)
            w[o] = *(const float4*)&sW[branch][jb + 8 * o][64 + ch * 4];
        #pragma unroll
        for (int ni = 0; ni < 2; ni++)
            #pragma unroll
            for (int o = 0; o < 4; o++) {
                acc[ni][o] = fmaf(v[ni].x, w[o].x, acc[ni][o]);
                acc[ni][o] = fmaf(v[ni].y, w[o].y, acc[ni][o]);
                acc[ni][o] = fmaf(v[ni].z, w[o].z, acc[ni][o]);
                acc[ni][o] = fmaf(v[ni].w, w[o].w, acc[ni][o]);
            }
    }

    #pragma unroll
    for (int ni = 0; ni < 2; ni++) {
        int n = nbase + ni;
        if (n < N_NODES) {
            #pragma unroll
            for (int o = 0; o < 4; o++)
                out[n * 64 + branch * 32 + jb + 8 * o] = tanhf(acc[ni][o]);
        }
    }
}

// ---------------- launch ----------------
extern "C" void kernel_launch(void* const* d_in, const int* in_sizes, int n_in,
                              void* d_out, int out_size)
{
    const float* x    = (const float*)d_in[0];
    const int* posEI  = (const int*)d_in[1];
    const int* negEI  = (const int*)d_in[2];
    const float* w1b  = (const float*)d_in[3];
    const float* b1b  = (const float*)d_in[4];
    const float* w1u  = (const float*)d_in[5];
    const float* b1u  = (const float*)d_in[6];
    const float* w2b  = (const float*)d_in[7];
    const float* b2b  = (const float*)d_in[8];
    const float* w2u  = (const float*)d_in[9];
    const float* b2u  = (const float*)d_in[10];
    float* out = (float*)d_out;

    int E = in_sizes[1] / 2;             // 1,600,000
    const int* posSrc = posEI;
    const int* posDst = posEI + E;
    const int* negSrc = negEI;
    const int* negDst = negEI + E;

    int zeroGrid = (N_NODES * 16 + 255) / 256;
    int aggGrid  = (E * 16 + 255) / 256;
    int linGrid  = (N_NODES + 31) / 32;   // 3125

    zero_layer1<<<zeroGrid, 256>>>();
    agg_kernel<<<aggGrid, 256>>>((const float4*)x, posSrc, posDst, E, 0, 0, 1);
    agg_kernel<<<aggGrid, 256>>>((const float4*)x, negSrc, negDst, E, 0, 1, 1);
    linear1_v4<<<linGrid, 256>>>(x, w1b, b1b, w1u, b1u);
    zero_layer2<<<zeroGrid, 256>>>();
    agg_kernel<<<aggGrid, 256>>>((const float4*)x, posSrc, posDst, E, 1, 0, 0);
    agg_kernel<<<aggGrid, 256>>>((const float4*)x, negSrc, negDst, E, 1, 1, 0);
    linear2_v4<<<linGrid, 256>>>(w2b, b2b, w2u, b2u, out);
}

// round 8
// speedup vs baseline: 1.0423x; 1.0423x over previous
#include <cuda_runtime.h>
#include <math.h>

#define N_NODES 100000
#define IN_DIM 64
#define HALF 32

// ---------------- scratch (device globals: allocation-free) ----------------
__device__ float4 g_aggP[N_NODES * 16];   // 100k x 64 floats
__device__ float4 g_aggN[N_NODES * 16];
__device__ float4 g_z[N_NODES * 16];      // tanh output of layer 1
__device__ float  g_cntP[N_NODES];
__device__ float  g_cntN[N_NODES];

// ---------------- zero kernels ----------------
__global__ void zero_layer1() {
    int i = blockIdx.x * blockDim.x + threadIdx.x;
    float4 z4 = make_float4(0.f, 0.f, 0.f, 0.f);
    if (i < N_NODES * 16) { g_aggP[i] = z4; g_aggN[i] = z4; }
    if (i < N_NODES)      { g_cntP[i] = 0.f; g_cntN[i] = 0.f; }
}
__global__ void zero_layer2() {
    int i = blockIdx.x * blockDim.x + threadIdx.x;
    float4 z4 = make_float4(0.f, 0.f, 0.f, 0.f);
    if (i < N_NODES * 16) { g_aggP[i] = z4; g_aggN[i] = z4; }
}

// ---------------- edge aggregation (proven round-2 version) ----------------
__global__ void __launch_bounds__(256)
agg_kernel(const float4* __restrict__ xfeat,
           const int* __restrict__ src, const int* __restrict__ dst,
           int nEdges, int featSel, int outSel, int doCnt)
{
    int t = blockIdx.x * blockDim.x + threadIdx.x;
    if (t >= nEdges * 16) return;
    int e = t >> 4;
    int c = t & 15;
    int s = __ldg(src + e);
    int d = __ldg(dst + e);
    const float4* feat = featSel ? (const float4*)g_z : xfeat;
    float4* out = outSel ? g_aggN : g_aggP;
    float4 v = __ldg(feat + s * 16 + c);
    float4* p = out + d * 16 + c;
    asm volatile("red.global.add.v4.f32 [%0], {%1,%2,%3,%4};"
                 :: "l"(p), "f"(v.x), "f"(v.y), "f"(v.z), "f"(v.w) : "memory");
    if (doCnt && c == 0) {
        float* cnt = outSel ? g_cntN : g_cntP;
        atomicAdd(cnt + d, 1.0f);
    }
}

// ---------------- layer 1: smem-staged, 4 nodes x 4 outputs / thread ----------------
// branch0 (j 0..31):  tanh( [aggP/cP, x] @ w1b + b1b )
// branch1 (j 32..63): tanh( [aggN/cN, x] @ w1u + b1u )
// j = branch*32 + jb + 8*o.  mean folded at staging time.
// dynamic smem layout: sW0[32*RS1] | sW1[32*RS1] | sB[64] | sAP[64*64] | sAN[64*64] | sX[64*64]
#define RS1 132
#define SM1_FLOATS (2 * 32 * RS1 + 64 + 3 * 64 * 64)
__global__ void __launch_bounds__(256)
linear1_v6(const float* __restrict__ x,
           const float* __restrict__ w1b, const float* __restrict__ b1b,
           const float* __restrict__ w1u, const float* __restrict__ b1u)
{
    extern __shared__ float sm1[];
    float* sW0 = sm1;
    float* sW1 = sW0 + 32 * RS1;
    float* sB  = sW1 + 32 * RS1;
    float* sAP = sB + 64;
    float* sAN = sAP + 64 * 64;
    float* sX  = sAN + 64 * 64;

    int tid = threadIdx.x;
    for (int i = tid; i < 128 * 32; i += 256) {
        int k = i >> 5, j = i & 31;
        sW0[j * RS1 + k] = w1b[i];
        sW1[j * RS1 + k] = w1u[i];
    }
    if (tid < 32) { sB[tid] = b1b[tid]; sB[tid + 32] = b1u[tid]; }

    int nbase = blockIdx.x * 64;
    // stage 64 node rows: aggP (scaled), aggN (scaled), x. fully coalesced.
    for (int idx = tid; idx < 1024; idx += 256) {
        int r = idx >> 4, c = idx & 15;
        int n = nbase + r; if (n > N_NODES - 1) n = N_NODES - 1;
        float invP = 1.0f / fmaxf(g_cntP[n], 1.0f);
        float invN = 1.0f / fmaxf(g_cntN[n], 1.0f);
        float4 vp = g_aggP[n * 16 + c];
        float4 vn = g_aggN[n * 16 + c];
        float4 vx = __ldg((const float4*)x + n * 16 + c);
        *(float4*)&sAP[r * 64 + c * 4] = make_float4(vp.x * invP, vp.y * invP, vp.z * invP, vp.w * invP);
        *(float4*)&sAN[r * 64 + c * 4] = make_float4(vn.x * invN, vn.y * invN, vn.z * invN, vn.w * invN);
        *(float4*)&sX[r * 64 + c * 4] = vx;
    }
    __syncthreads();

    int jg = tid & 15, ng = tid >> 4;
    int branch = jg >> 3, jb = jg & 7;
    const float* sWb = branch ? sW1 : sW0;
    const float* sA  = branch ? sAN : sAP;
    float* zout = (float*)g_z;
    int rbase = ng * 4;

    float acc[4][4];
    #pragma unroll
    for (int ni = 0; ni < 4; ni++)
        #pragma unroll
        for (int o = 0; o < 4; o++)
            acc[ni][o] = sB[branch * 32 + jb + 8 * o];

    // region A: scaled agg (k = 0..63)
    #pragma unroll 4
    for (int ch = 0; ch < 16; ch++) {
        float4 v[4], w[4];
        #pragma unroll
        for (int ni = 0; ni < 4; ni++)
            v[ni] = *(const float4*)&sA[(rbase + ni) * 64 + ch * 4];
        #pragma unroll
        for (int o = 0; o < 4; o++)
            w[o] = *(const float4*)&sWb[(jb + 8 * o) * RS1 + ch * 4];
        #pragma unroll
        for (int ni = 0; ni < 4; ni++)
            #pragma unroll
            for (int o = 0; o < 4; o++) {
                acc[ni][o] = fmaf(v[ni].x, w[o].x, acc[ni][o]);
                acc[ni][o] = fmaf(v[ni].y, w[o].y, acc[ni][o]);
                acc[ni][o] = fmaf(v[ni].z, w[o].z, acc[ni][o]);
                acc[ni][o] = fmaf(v[ni].w, w[o].w, acc[ni][o]);
            }
    }
    // region B: self features (k = 64..127)
    #pragma unroll 4
    for (int ch = 0; ch < 16; ch++) {
        float4 v[4], w[4];
        #pragma unroll
        for (int ni = 0; ni < 4; ni++)
            v[ni] = *(const float4*)&sX[(rbase + ni) * 64 + ch * 4];
        #pragma unroll
        for (int o = 0; o < 4; o++)
            w[o] = *(const float4*)&sWb[(jb + 8 * o) * RS1 + 64 + ch * 4];
        #pragma unroll
        for (int ni = 0; ni < 4; ni++)
            #pragma unroll
            for (int o = 0; o < 4; o++) {
                acc[ni][o] = fmaf(v[ni].x, w[o].x, acc[ni][o]);
                acc[ni][o] = fmaf(v[ni].y, w[o].y, acc[ni][o]);
                acc[ni][o] = fmaf(v[ni].z, w[o].z, acc[ni][o]);
                acc[ni][o] = fmaf(v[ni].w, w[o].w, acc[ni][o]);
            }
    }

    #pragma unroll
    for (int ni = 0; ni < 4; ni++) {
        int n = nbase + rbase + ni;
        if (n < N_NODES) {
            #pragma unroll
            for (int o = 0; o < 4; o++)
                zout[n * 64 + branch * 32 + jb + 8 * o] = tanhf(acc[ni][o]);
        }
    }
}

// ---------------- layer 2: smem-staged, 4 nodes x 4 outputs / thread ----------------
// branch0: [aggP[0:32]/cP, aggN[32:64]/cN, z[0:32] ] @ w2b + b2b
// branch1: [aggP[32:64]/cP, aggN[0:32]/cN, z[32:64]] @ w2u + b2u
#define RS2 100
#define SM2_FLOATS (2 * 32 * RS2 + 64 + 3 * 64 * 64)
__global__ void __launch_bounds__(256)
linear2_v6(const float* __restrict__ w2b, const float* __restrict__ b2b,
           const float* __restrict__ w2u, const float* __restrict__ b2u,
           float* __restrict__ out)
{
    extern __shared__ float sm2[];
    float* sW0 = sm2;
    float* sW1 = sW0 + 32 * RS2;
    float* sB  = sW1 + 32 * RS2;
    float* sAP = sB + 64;
    float* sAN = sAP + 64 * 64;
    float* sZ  = sAN + 64 * 64;

    int tid = threadIdx.x;
    for (int i = tid; i < 96 * 32; i += 256) {
        int k = i >> 5, j = i & 31;
        sW0[j * RS2 + k] = w2b[i];
        sW1[j * RS2 + k] = w2u[i];
    }
    if (tid < 32) { sB[tid] = b2b[tid]; sB[tid + 32] = b2u[tid]; }

    int nbase = blockIdx.x * 64;
    const float4* z4 = (const float4*)g_z;
    for (int idx = tid; idx < 1024; idx += 256) {
        int r = idx >> 4, c = idx & 15;
        int n = nbase + r; if (n > N_NODES - 1) n = N_NODES - 1;
        float invP = 1.0f / fmaxf(g_cntP[n], 1.0f);
        float invN = 1.0f / fmaxf(g_cntN[n], 1.0f);
        float4 vp = g_aggP[n * 16 + c];
        float4 vn = g_aggN[n * 16 + c];
        float4 vz = z4[n * 16 + c];
        *(float4*)&sAP[r * 64 + c * 4] = make_float4(vp.x * invP, vp.y * invP, vp.z * invP, vp.w * invP);
        *(float4*)&sAN[r * 64 + c * 4] = make_float4(vn.x * invN, vn.y * invN, vn.z * invN, vn.w * invN);
        *(float4*)&sZ[r * 64 + c * 4] = vz;
    }
    __syncthreads();

    int jg = tid & 15, ng = tid >> 4;
    int branch = jg >> 3, jb = jg & 7;
    const float* sWb = branch ? sW1 : sW0;
    int offA = branch * 32;          // aggP slice
    int offB = (1 - branch) * 32;    // aggN slice
    int offC = branch * 32;          // z slice
    int rbase = ng * 4;

    float acc[4][4];
    #pragma unroll
    for (int ni = 0; ni < 4; ni++)
        #pragma unroll
        for (int o = 0; o < 4; o++)
            acc[ni][o] = sB[branch * 32 + jb + 8 * o];

    // segment A (k = 0..31): aggP slice
    #pragma unroll
    for (int ch = 0; ch < 8; ch++) {
        float4 v[4], w[4];
        #pragma unroll
        for (int ni = 0; ni < 4; ni++)
            v[ni] = *(const float4*)&sAP[(rbase + ni) * 64 + offA + ch * 4];
        #pragma unroll
        for (int o = 0; o < 4; o++)
            w[o] = *(const float4*)&sWb[(jb + 8 * o) * RS2 + ch * 4];
        #pragma unroll
        for (int ni = 0; ni < 4; ni++)
            #pragma unroll
            for (int o = 0; o < 4; o++) {
                acc[ni][o] = fmaf(v[ni].x, w[o].x, acc[ni][o]);
                acc[ni][o] = fmaf(v[ni].y, w[o].y, acc[ni][o]);
                acc[ni][o] = fmaf(v[ni].z, w[o].z, acc[ni][o]);
                acc[ni][o] = fmaf(v[ni].w, w[o].w, acc[ni][o]);
            }
    }
    // segment B (k = 32..63): aggN slice
    #pragma unroll
    for (int ch = 0; ch < 8; ch++) {
        float4 v[4], w[4];
        #pragma unroll
        for (int ni = 0; ni < 4; ni++)
            v[ni] = *(const float4*)&sAN[(rbase + ni) * 64 + offB + ch * 4];
        #pragma unroll
        for (int o = 0; o < 4; o++)
            w[o] = *(const float4*)&sWb[(jb + 8 * o) * RS2 + 32 + ch * 4];
        #pragma unroll
        for (int ni = 0; ni < 4; ni++)
            #pragma unroll
            for (int o = 0; o < 4; o++) {
                acc[ni][o] = fmaf(v[ni].x, w[o].x, acc[ni][o]);
                acc[ni][o] = fmaf(v[ni].y, w[o].y, acc[ni][o]);
                acc[ni][o] = fmaf(v[ni].z, w[o].z, acc[ni][o]);
                acc[ni][o] = fmaf(v[ni].w, w[o].w, acc[ni][o]);
            }
    }
    // segment C (k = 64..95): z slice
    #pragma unroll
    for (int ch = 0; ch < 8; ch++) {
        float4 v[4], w[4];
        #pragma unroll
        for (int ni = 0; ni < 4; ni++)
            v[ni] = *(const float4*)&sZ[(rbase + ni) * 64 + offC + ch * 4];
        #pragma unroll
        for (int o = 0; o < 4; o++)
            w[o] = *(const float4*)&sWb[(jb + 8 * o) * RS2 + 64 + ch * 4];
        #pragma unroll
        for (int ni = 0; ni < 4; ni++)
            #pragma unroll
            for (int o = 0; o < 4; o++) {
                acc[ni][o] = fmaf(v[ni].x, w[o].x, acc[ni][o]);
                acc[ni][o] = fmaf(v[ni].y, w[o].y, acc[ni][o]);
                acc[ni][o] = fmaf(v[ni].z, w[o].z, acc[ni][o]);
                acc[ni][o] = fmaf(v[ni].w, w[o].w, acc[ni][o]);
            }
    }

    #pragma unroll
    for (int ni = 0; ni < 4; ni++) {
        int n = nbase + rbase + ni;
        if (n < N_NODES) {
            #pragma unroll
            for (int o = 0; o < 4; o++)
                out[n * 64 + branch * 32 + jb + 8 * o] = tanhf(acc[ni][o]);
        }
    }
}

// ---------------- launch ----------------
extern "C" void kernel_launch(void* const* d_in, const int* in_sizes, int n_in,
                              void* d_out, int out_size)
{
    const float* x    = (const float*)d_in[0];
    const int* posEI  = (const int*)d_in[1];
    const int* negEI  = (const int*)d_in[2];
    const float* w1b  = (const float*)d_in[3];
    const float* b1b  = (const float*)d_in[4];
    const float* w1u  = (const float*)d_in[5];
    const float* b1u  = (const float*)d_in[6];
    const float* w2b  = (const float*)d_in[7];
    const float* b2b  = (const float*)d_in[8];
    const float* w2u  = (const float*)d_in[9];
    const float* b2u  = (const float*)d_in[10];
    float* out = (float*)d_out;

    int E = in_sizes[1] / 2;             // 1,600,000
    const int* posSrc = posEI;
    const int* posDst = posEI + E;
    const int* negSrc = negEI;
    const int* negDst = negEI + E;

    int zeroGrid = (N_NODES * 16 + 255) / 256;
    int aggGrid  = (E * 16 + 255) / 256;
    int linGrid  = (N_NODES + 63) / 64;   // 1563

    int sm1Bytes = SM1_FLOATS * 4;   // 83,200
    int sm2Bytes = SM2_FLOATS * 4;   // 75,008
    cudaFuncSetAttribute(linear1_v6, cudaFuncAttributeMaxDynamicSharedMemorySize, sm1Bytes);
    cudaFuncSetAttribute(linear2_v6, cudaFuncAttributeMaxDynamicSharedMemorySize, sm2Bytes);

    zero_layer1<<<zeroGrid, 256>>>();
    agg_kernel<<<aggGrid, 256>>>((const float4*)x, posSrc, posDst, E, 0, 0, 1);
    agg_kernel<<<aggGrid, 256>>>((const float4*)x, negSrc, negDst, E, 0, 1, 1);
    linear1_v6<<<linGrid, 256, sm1Bytes>>>(x, w1b, b1b, w1u, b1u);
    zero_layer2<<<zeroGrid, 256>>>();
    agg_kernel<<<aggGrid, 256>>>((const float4*)x, posSrc, posDst, E, 1, 0, 0);
    agg_kernel<<<aggGrid, 256>>>((const float4*)x, negSrc, negDst, E, 1, 1, 0);
    linear2_v6<<<linGrid, 256, sm2Bytes>>>(w2b, b2b, w2u, b2u, out);
}

// round 9
// speedup vs baseline: 1.0576x; 1.0147x over previous
#include <cuda_runtime.h>
#include <math.h>

#define N_NODES 100000
#define IN_DIM 64
#define HALF 32

// ---------------- scratch (device globals: allocation-free, proven set) ----------------
__device__ float4 g_aggP[N_NODES * 16];   // 100k x 64 floats
__device__ float4 g_aggN[N_NODES * 16];
__device__ float4 g_z[N_NODES * 16];      // tanh output of layer 1
__device__ float  g_cntP[N_NODES];
__device__ float  g_cntN[N_NODES];

__device__ __forceinline__ float ftanh(float v) {
    float e = __expf(2.0f * v);
    return 1.0f - 2.0f / (e + 1.0f);
}

// ---------------- zero kernels ----------------
__global__ void zero_layer1() {
    int i = blockIdx.x * blockDim.x + threadIdx.x;
    float4 z4 = make_float4(0.f, 0.f, 0.f, 0.f);
    if (i < N_NODES * 16) { g_aggP[i] = z4; g_aggN[i] = z4; }
    if (i < N_NODES)      { g_cntP[i] = 0.f; g_cntN[i] = 0.f; }
}
__global__ void zero_layer2() {
    int i = blockIdx.x * blockDim.x + threadIdx.x;
    float4 z4 = make_float4(0.f, 0.f, 0.f, 0.f);
    if (i < N_NODES * 16) { g_aggP[i] = z4; g_aggN[i] = z4; }
}

// ---------------- edge aggregation (proven round-2 version) ----------------
__global__ void __launch_bounds__(256)
agg_kernel(const float4* __restrict__ xfeat,
           const int* __restrict__ src, const int* __restrict__ dst,
           int nEdges, int featSel, int outSel, int doCnt)
{
    int t = blockIdx.x * blockDim.x + threadIdx.x;
    if (t >= nEdges * 16) return;
    int e = t >> 4;
    int c = t & 15;
    int s = __ldg(src + e);
    int d = __ldg(dst + e);
    const float4* feat = featSel ? (const float4*)g_z : xfeat;
    float4* out = outSel ? g_aggN : g_aggP;
    float4 v = __ldg(feat + s * 16 + c);
    float4* p = out + d * 16 + c;
    asm volatile("red.global.add.v4.f32 [%0], {%1,%2,%3,%4};"
                 :: "l"(p), "f"(v.x), "f"(v.y), "f"(v.z), "f"(v.w) : "memory");
    if (doCnt && c == 0) {
        float* cnt = outSel ? g_cntN : g_cntP;
        atomicAdd(cnt + d, 1.0f);
    }
}

// ---------------- in-place mean fold: agg *= 1/max(cnt,1) for both buffers ----------------
__global__ void __launch_bounds__(256)
scale_kernel()
{
    int i = blockIdx.x * blockDim.x + threadIdx.x;
    if (i >= N_NODES * 32) return;
    int isN = (i >= N_NODES * 16);
    int j = isN ? i - N_NODES * 16 : i;
    int n = j >> 4;
    float cnt = isN ? g_cntN[n] : g_cntP[n];
    float inv = 1.0f / fmaxf(cnt, 1.0f);
    float4* buf = isN ? g_aggN : g_aggP;
    float4 v = buf[j];
    buf[j] = make_float4(v.x * inv, v.y * inv, v.z * inv, v.w * inv);
}

// ---------------- layer 1: weights-in-smem GEMM, 4 nodes x 4 outputs / thread ----------------
// branch0 (j 0..31):  tanh( [aggP, x] @ w1b + b1b )   (agg pre-scaled by 1/cnt)
// branch1 (j 32..63): tanh( [aggN, x] @ w1u + b1u )
// j = branch*32 + jb + 8*o
#define RS1 132
__global__ void __launch_bounds__(256, 4)
linear1_v7(const float* __restrict__ x,
           const float* __restrict__ w1b, const float* __restrict__ b1b,
           const float* __restrict__ w1u, const float* __restrict__ b1u)
{
    __shared__ float sW[2][32][RS1];   // sW[branch][j][k], 33.8KB
    __shared__ float sB[64];
    int tid = threadIdx.x;
    for (int i = tid; i < 128 * 32; i += 256) {
        int k = i >> 5, j = i & 31;
        sW[0][j][k] = w1b[i];
        sW[1][j][k] = w1u[i];
    }
    if (tid < 32) { sB[tid] = b1b[tid]; sB[tid + 32] = b1u[tid]; }
    __syncthreads();

    int jg = tid & 15, ng = tid >> 4;
    int branch = jg >> 3, jb = jg & 7;
    const float* agg = branch ? (const float*)g_aggN : (const float*)g_aggP;
    float* zout = (float*)g_z;

    int nbase = blockIdx.x * 64 + ng * 4;
    int nidx[4];
    #pragma unroll
    for (int ni = 0; ni < 4; ni++) {
        int n = nbase + ni; if (n > N_NODES - 1) n = N_NODES - 1;
        nidx[ni] = n;
    }

    float acc[4][4];
    #pragma unroll
    for (int ni = 0; ni < 4; ni++)
        #pragma unroll
        for (int o = 0; o < 4; o++)
            acc[ni][o] = sB[branch * 32 + jb + 8 * o];

    // region A: pre-scaled agg (k = 0..63)
    #pragma unroll 4
    for (int ch = 0; ch < 16; ch++) {
        float4 v[4], w[4];
        #pragma unroll
        for (int ni = 0; ni < 4; ni++)
            v[ni] = __ldg((const float4*)(agg + nidx[ni] * 64 + ch * 4));
        #pragma unroll
        for (int o = 0; o < 4; o++)
            w[o] = *(const float4*)&sW[branch][jb + 8 * o][ch * 4];
        #pragma unroll
        for (int ni = 0; ni < 4; ni++)
            #pragma unroll
            for (int o = 0; o < 4; o++) {
                acc[ni][o] = fmaf(v[ni].x, w[o].x, acc[ni][o]);
                acc[ni][o] = fmaf(v[ni].y, w[o].y, acc[ni][o]);
                acc[ni][o] = fmaf(v[ni].z, w[o].z, acc[ni][o]);
                acc[ni][o] = fmaf(v[ni].w, w[o].w, acc[ni][o]);
            }
    }
    // region B: self features x (k = 64..127)
    #pragma unroll 4
    for (int ch = 0; ch < 16; ch++) {
        float4 v[4], w[4];
        #pragma unroll
        for (int ni = 0; ni < 4; ni++)
            v[ni] = __ldg((const float4*)(x + nidx[ni] * 64 + ch * 4));
        #pragma unroll
        for (int o = 0; o < 4; o++)
            w[o] = *(const float4*)&sW[branch][jb + 8 * o][64 + ch * 4];
        #pragma unroll
        for (int ni = 0; ni < 4; ni++)
            #pragma unroll
            for (int o = 0; o < 4; o++) {
                acc[ni][o] = fmaf(v[ni].x, w[o].x, acc[ni][o]);
                acc[ni][o] = fmaf(v[ni].y, w[o].y, acc[ni][o]);
                acc[ni][o] = fmaf(v[ni].z, w[o].z, acc[ni][o]);
                acc[ni][o] = fmaf(v[ni].w, w[o].w, acc[ni][o]);
            }
    }

    #pragma unroll
    for (int ni = 0; ni < 4; ni++) {
        int n = nbase + ni;
        if (n < N_NODES) {
            #pragma unroll
            for (int o = 0; o < 4; o++)
                zout[n * 64 + branch * 32 + jb + 8 * o] = ftanh(acc[ni][o]);
        }
    }
}

// ---------------- layer 2: weights-in-smem GEMM, 4 nodes x 4 outputs / thread ----------------
// branch0: [aggP[0:32], aggN[32:64], z[0:32] ] @ w2b + b2b   (aggs pre-scaled)
// branch1: [aggP[32:64], aggN[0:32], z[32:64]] @ w2u + b2u
#define RS2 100
__global__ void __launch_bounds__(256, 4)
linear2_v7(const float* __restrict__ w2b, const float* __restrict__ b2b,
           const float* __restrict__ w2u, const float* __restrict__ b2u,
           float* __restrict__ out)
{
    __shared__ float sW[2][32][RS2];   // 25.6KB
    __shared__ float sB[64];
    int tid = threadIdx.x;
    for (int i = tid; i < 96 * 32; i += 256) {
        int k = i >> 5, j = i & 31;
        sW[0][j][k] = w2b[i];
        sW[1][j][k] = w2u[i];
    }
    if (tid < 32) { sB[tid] = b2b[tid]; sB[tid + 32] = b2u[tid]; }
    __syncthreads();

    int jg = tid & 15, ng = tid >> 4;
    int branch = jg >> 3, jb = jg & 7;
    const float* aggP = (const float*)g_aggP;
    const float* aggN = (const float*)g_aggN;
    const float* z = (const float*)g_z;

    int offA = branch * 32;          // aggP column offset
    int offB = (1 - branch) * 32;    // aggN column offset
    int offC = branch * 32;          // z column offset

    int nbase = blockIdx.x * 64 + ng * 4;
    int nidx[4];
    #pragma unroll
    for (int ni = 0; ni < 4; ni++) {
        int n = nbase + ni; if (n > N_NODES - 1) n = N_NODES - 1;
        nidx[ni] = n;
    }

    float acc[4][4];
    #pragma unroll
    for (int ni = 0; ni < 4; ni++)
        #pragma unroll
        for (int o = 0; o < 4; o++)
            acc[ni][o] = sB[branch * 32 + jb + 8 * o];

    // segment A (k = 0..31): aggP slice
    #pragma unroll
    for (int ch = 0; ch < 8; ch++) {
        float4 v[4], w[4];
        #pragma unroll
        for (int ni = 0; ni < 4; ni++)
            v[ni] = __ldg((const float4*)(aggP + nidx[ni] * 64 + offA + ch * 4));
        #pragma unroll
        for (int o = 0; o < 4; o++)
            w[o] = *(const float4*)&sW[branch][jb + 8 * o][ch * 4];
        #pragma unroll
        for (int ni = 0; ni < 4; ni++)
            #pragma unroll
            for (int o = 0; o < 4; o++) {
                acc[ni][o] = fmaf(v[ni].x, w[o].x, acc[ni][o]);
                acc[ni][o] = fmaf(v[ni].y, w[o].y, acc[ni][o]);
                acc[ni][o] = fmaf(v[ni].z, w[o].z, acc[ni][o]);
                acc[ni][o] = fmaf(v[ni].w, w[o].w, acc[ni][o]);
            }
    }
    // segment B (k = 32..63): aggN slice
    #pragma unroll
    for (int ch = 0; ch < 8; ch++) {
        float4 v[4], w[4];
        #pragma unroll
        for (int ni = 0; ni < 4; ni++)
            v[ni] = __ldg((const float4*)(aggN + nidx[ni] * 64 + offB + ch * 4));
        #pragma unroll
        for (int o = 0; o < 4; o++)
            w[o] = *(const float4*)&sW[branch][jb + 8 * o][32 + ch * 4];
        #pragma unroll
        for (int ni = 0; ni < 4; ni++)
            #pragma unroll
            for (int o = 0; o < 4; o++) {
                acc[ni][o] = fmaf(v[ni].x, w[o].x, acc[ni][o]);
                acc[ni][o] = fmaf(v[ni].y, w[o].y, acc[ni][o]);
                acc[ni][o] = fmaf(v[ni].z, w[o].z, acc[ni][o]);
                acc[ni][o] = fmaf(v[ni].w, w[o].w, acc[ni][o]);
            }
    }
    // segment C (k = 64..95): z slice
    #pragma unroll
    for (int ch = 0; ch < 8; ch++) {
        float4 v[4], w[4];
        #pragma unroll
        for (int ni = 0; ni < 4; ni++)
            v[ni] = __ldg((const float4*)(z + nidx[ni] * 64 + offC + ch * 4));
        #pragma unroll
        for (int o = 0; o < 4; o++)
            w[o] = *(const float4*)&sW[branch][jb + 8 * o][64 + ch * 4];
        #pragma unroll
        for (int ni = 0; ni < 4; ni++)
            #pragma unroll
            for (int o = 0; o < 4; o++) {
                acc[ni][o] = fmaf(v[ni].x, w[o].x, acc[ni][o]);
                acc[ni][o] = fmaf(v[ni].y, w[o].y, acc[ni][o]);
                acc[ni][o] = fmaf(v[ni].z, w[o].z, acc[ni][o]);
                acc[ni][o] = fmaf(v[ni].w, w[o].w, acc[ni][o]);
            }
    }

    #pragma unroll
    for (int ni = 0; ni < 4; ni++) {
        int n = nbase + ni;
        if (n < N_NODES) {
            #pragma unroll
            for (int o = 0; o < 4; o++)
                out[n * 64 + branch * 32 + jb + 8 * o] = ftanh(acc[ni][o]);
        }
    }
}

// ---------------- launch ----------------
extern "C" void kernel_launch(void* const* d_in, const int* in_sizes, int n_in,
                              void* d_out, int out_size)
{
    const float* x    = (const float*)d_in[0];
    const int* posEI  = (const int*)d_in[1];
    const int* negEI  = (const int*)d_in[2];
    const float* w1b  = (const float*)d_in[3];
    const float* b1b  = (const float*)d_in[4];
    const float* w1u  = (const float*)d_in[5];
    const float* b1u  = (const float*)d_in[6];
    const float* w2b  = (const float*)d_in[7];
    const float* b2b  = (const float*)d_in[8];
    const float* w2u  = (const float*)d_in[9];
    const float* b2u  = (const float*)d_in[10];
    float* out = (float*)d_out;

    int E = in_sizes[1] / 2;             // 1,600,000
    const int* posSrc = posEI;
    const int* posDst = posEI + E;
    const int* negSrc = negEI;
    const int* negDst = negEI + E;

    int zeroGrid  = (N_NODES * 16 + 255) / 256;
    int aggGrid   = (E * 16 + 255) / 256;
    int scaleGrid = (N_NODES * 32 + 255) / 256;
    int linGrid   = (N_NODES + 63) / 64;   // 1563

    zero_layer1<<<zeroGrid, 256>>>();
    agg_kernel<<<aggGrid, 256>>>((const float4*)x, posSrc, posDst, E, 0, 0, 1);
    agg_kernel<<<aggGrid, 256>>>((const float4*)x, negSrc, negDst, E, 0, 1, 1);
    scale_kernel<<<scaleGrid, 256>>>();
    linear1_v7<<<linGrid, 256>>>(x, w1b, b1b, w1u, b1u);
    zero_layer2<<<zeroGrid, 256>>>();
    agg_kernel<<<aggGrid, 256>>>((const float4*)x, posSrc, posDst, E, 1, 0, 0);
    agg_kernel<<<aggGrid, 256>>>((const float4*)x, negSrc, negDst, E, 1, 1, 0);
    scale_kernel<<<scaleGrid, 256>>>();
    linear2_v7<<<linGrid, 256>>>(w2b, b2b, w2u, b2u, out);
}

// round 10
// speedup vs baseline: 1.1855x; 1.1210x over previous
#include <cuda_runtime.h>
#include <math.h>

#define N_NODES 100000
#define IN_DIM 64
#define HALF 32

// ---------------- scratch (device globals: allocation-free) ----------------
__device__ float4 g_xT[N_NODES * 16];     // [x@W1b_agg | x@W1u_agg]  100k x 64
__device__ float4 g_agg1P[N_NODES * 8];   // 32-dim agg of xT[:,0:32] over pos
__device__ float4 g_agg1N[N_NODES * 8];   // 32-dim agg of xT[:,32:64] over neg
__device__ float4 g_z[N_NODES * 16];      // layer-1 output, 100k x 64
__device__ float4 g_zT[N_NODES * 32];     // [u | v] transformed z, 100k x 128
__device__ float4 g_agg2P[N_NODES * 16];  // 64-dim agg of zT[:,0:64] over pos
__device__ float4 g_agg2N[N_NODES * 16];  // 64-dim agg of zT[:,64:128] over neg
__device__ float  g_cntP[N_NODES];
__device__ float  g_cntN[N_NODES];

__device__ __forceinline__ float ftanh(float v) {
    float e = __expf(2.0f * v);
    return 1.0f - 2.0f / (e + 1.0f);
}

// ---------------- zero kernels ----------------
__global__ void __launch_bounds__(256) zero1() {
    int i = blockIdx.x * blockDim.x + threadIdx.x;
    float4 z4 = make_float4(0.f, 0.f, 0.f, 0.f);
    if (i < N_NODES * 8) { g_agg1P[i] = z4; g_agg1N[i] = z4; }
    if (i < N_NODES)     { g_cntP[i] = 0.f; g_cntN[i] = 0.f; }
}
__global__ void __launch_bounds__(256) zero2() {
    int i = blockIdx.x * blockDim.x + threadIdx.x;
    float4 z4 = make_float4(0.f, 0.f, 0.f, 0.f);
    if (i < N_NODES * 16) { g_agg2P[i] = z4; g_agg2N[i] = z4; }
}

// ---------------- edge aggregation over a column slice (proven red.global pattern) ----------------
// layer 1: 8 float4 chunks/edge from g_xT (pos: cols 0:32, neg: 32:64) -> g_agg1{P,N}, +count
// layer 2: 16 float4 chunks/edge from g_zT (pos: cols 0:64, neg: 64:128) -> g_agg2{P,N}
__global__ void __launch_bounds__(256)
agg_slice(const int* __restrict__ src, const int* __restrict__ dst, int E,
          int layer, int isNeg)
{
    int t = blockIdx.x * blockDim.x + threadIdx.x;
    if (layer == 1) {
        if (t >= E * 8) return;
        int e = t >> 3, c = t & 7;
        int s = __ldg(src + e);
        int d = __ldg(dst + e);
        float4 v = __ldg(g_xT + s * 16 + (isNeg ? 8 : 0) + c);
        float4* p = (isNeg ? g_agg1N : g_agg1P) + d * 8 + c;
        asm volatile("red.global.add.v4.f32 [%0], {%1,%2,%3,%4};"
                     :: "l"(p), "f"(v.x), "f"(v.y), "f"(v.z), "f"(v.w) : "memory");
        if (c == 0) atomicAdd((isNeg ? g_cntN : g_cntP) + d, 1.0f);
    } else {
        if (t >= E * 16) return;
        int e = t >> 4, c = t & 15;
        int s = __ldg(src + e);
        int d = __ldg(dst + e);
        float4 v = __ldg(g_zT + s * 32 + (isNeg ? 16 : 0) + c);
        float4* p = (isNeg ? g_agg2N : g_agg2P) + d * 16 + c;
        asm volatile("red.global.add.v4.f32 [%0], {%1,%2,%3,%4};"
                     :: "l"(p), "f"(v.x), "f"(v.y), "f"(v.z), "f"(v.w) : "memory");
    }
}

// ---------------- transform1: xT = [x@w1b(rows 0:64) | x@w1u(rows 0:64)] ----------------
#define KS1 68
__global__ void __launch_bounds__(256, 4)
transform1_kernel(const float* __restrict__ x,
                  const float* __restrict__ w1b, const float* __restrict__ w1u)
{
    __shared__ float sW[2][32][KS1];   // sW[branch][j][k], k<64
    int tid = threadIdx.x;
    for (int i = tid; i < 64 * 32; i += 256) {
        int k = i >> 5, j = i & 31;
        sW[0][j][k] = w1b[i];
        sW[1][j][k] = w1u[i];
    }
    __syncthreads();

    int jg = tid & 15, ng = tid >> 4;
    int branch = jg >> 3, jb = jg & 7;
    int nbase = blockIdx.x * 64 + ng * 4;
    int nidx[4];
    #pragma unroll
    for (int ni = 0; ni < 4; ni++) {
        int n = nbase + ni; if (n > N_NODES - 1) n = N_NODES - 1;
        nidx[ni] = n;
    }

    float acc[4][4];
    #pragma unroll
    for (int ni = 0; ni < 4; ni++)
        #pragma unroll
        for (int o = 0; o < 4; o++) acc[ni][o] = 0.f;

    #pragma unroll 4
    for (int ch = 0; ch < 16; ch++) {
        float4 v[4], w[4];
        #pragma unroll
        for (int ni = 0; ni < 4; ni++)
            v[ni] = __ldg((const float4*)(x + nidx[ni] * 64 + ch * 4));
        #pragma unroll
        for (int o = 0; o < 4; o++)
            w[o] = *(const float4*)&sW[branch][jb + 8 * o][ch * 4];
        #pragma unroll
        for (int ni = 0; ni < 4; ni++)
            #pragma unroll
            for (int o = 0; o < 4; o++) {
                acc[ni][o] = fmaf(v[ni].x, w[o].x, acc[ni][o]);
                acc[ni][o] = fmaf(v[ni].y, w[o].y, acc[ni][o]);
                acc[ni][o] = fmaf(v[ni].z, w[o].z, acc[ni][o]);
                acc[ni][o] = fmaf(v[ni].w, w[o].w, acc[ni][o]);
            }
    }

    float* xT = (float*)g_xT;
    #pragma unroll
    for (int ni = 0; ni < 4; ni++) {
        int n = nbase + ni;
        if (n < N_NODES) {
            #pragma unroll
            for (int o = 0; o < 4; o++)
                xT[n * 64 + branch * 32 + jb + 8 * o] = acc[ni][o];
        }
    }
}

// ---------------- linear1: z = tanh(agg1*inv + x@Wself + b) ----------------
__global__ void __launch_bounds__(256, 4)
linear1_lite(const float* __restrict__ x,
             const float* __restrict__ w1b, const float* __restrict__ b1b,
             const float* __restrict__ w1u, const float* __restrict__ b1u)
{
    __shared__ float sW[2][32][KS1];   // self rows 64:127
    __shared__ float sB[64];
    int tid = threadIdx.x;
    for (int i = tid; i < 64 * 32; i += 256) {
        int k = i >> 5, j = i & 31;
        sW[0][j][k] = w1b[2048 + i];
        sW[1][j][k] = w1u[2048 + i];
    }
    if (tid < 32) { sB[tid] = b1b[tid]; sB[tid + 32] = b1u[tid]; }
    __syncthreads();

    int jg = tid & 15, ng = tid >> 4;
    int branch = jg >> 3, jb = jg & 7;
    int nbase = blockIdx.x * 64 + ng * 4;
    int nidx[4];
    #pragma unroll
    for (int ni = 0; ni < 4; ni++) {
        int n = nbase + ni; if (n > N_NODES - 1) n = N_NODES - 1;
        nidx[ni] = n;
    }

    float acc[4][4];
    #pragma unroll
    for (int ni = 0; ni < 4; ni++)
        #pragma unroll
        for (int o = 0; o < 4; o++)
            acc[ni][o] = sB[branch * 32 + jb + 8 * o];

    #pragma unroll 4
    for (int ch = 0; ch < 16; ch++) {
        float4 v[4], w[4];
        #pragma unroll
        for (int ni = 0; ni < 4; ni++)
            v[ni] = __ldg((const float4*)(x + nidx[ni] * 64 + ch * 4));
        #pragma unroll
        for (int o = 0; o < 4; o++)
            w[o] = *(const float4*)&sW[branch][jb + 8 * o][ch * 4];
        #pragma unroll
        for (int ni = 0; ni < 4; ni++)
            #pragma unroll
            for (int o = 0; o < 4; o++) {
                acc[ni][o] = fmaf(v[ni].x, w[o].x, acc[ni][o]);
                acc[ni][o] = fmaf(v[ni].y, w[o].y, acc[ni][o]);
                acc[ni][o] = fmaf(v[ni].z, w[o].z, acc[ni][o]);
                acc[ni][o] = fmaf(v[ni].w, w[o].w, acc[ni][o]);
            }
    }

    const float* agg = branch ? (const float*)g_agg1N : (const float*)g_agg1P;
    const float* cnt = branch ? g_cntN : g_cntP;
    float* zout = (float*)g_z;
    #pragma unroll
    for (int ni = 0; ni < 4; ni++) {
        int n = nbase + ni;
        if (n < N_NODES) {
            float inv = 1.0f / fmaxf(cnt[n], 1.0f);
            #pragma unroll
            for (int o = 0; o < 4; o++) {
                float a = __ldg(agg + n * 32 + jb + 8 * o);
                zout[n * 64 + branch * 32 + jb + 8 * o] = ftanh(acc[ni][o] + a * inv);
            }
        }
    }
}

// ---------------- transform2: zT = [u | v] ----------------
// u[0:32]=zp@w2b[0:32]   u[32:64]=zn@w2u[0:32]
// v[0:32]=zn@w2b[32:64]  v[32:64]=zp@w2u[32:64]
// quadrant q: z-half h, weight matrix wb, weight-row offset ro
__global__ void __launch_bounds__(256, 4)
transform2_kernel(const float* __restrict__ w2b, const float* __restrict__ w2u)
{
    __shared__ float sW[2][32][KS1];   // w2b/w2u rows 0:64
    int tid = threadIdx.x;
    for (int i = tid; i < 64 * 32; i += 256) {
        int k = i >> 5, j = i & 31;
        sW[0][j][k] = w2b[i];
        sW[1][j][k] = w2u[i];
    }
    __syncthreads();

    int jg = tid & 31, ng = tid >> 5;
    int q = jg >> 3, jb = jg & 7;
    int h  = (q == 1 || q == 2) ? 1 : 0;
    int wb = (q == 0 || q == 2) ? 0 : 1;
    int ro = (q >= 2) ? 32 : 0;
    int nbase = blockIdx.x * 32 + ng * 4;
    int nidx[4];
    #pragma unroll
    for (int ni = 0; ni < 4; ni++) {
        int n = nbase + ni; if (n > N_NODES - 1) n = N_NODES - 1;
        nidx[ni] = n;
    }

    const float* z = (const float*)g_z;
    float acc[4][4];
    #pragma unroll
    for (int ni = 0; ni < 4; ni++)
        #pragma unroll
        for (int o = 0; o < 4; o++) acc[ni][o] = 0.f;

    #pragma unroll
    for (int ch = 0; ch < 8; ch++) {
        float4 v[4], w[4];
        #pragma unroll
        for (int ni = 0; ni < 4; ni++)
            v[ni] = __ldg((const float4*)(z + nidx[ni] * 64 + h * 32 + ch * 4));
        #pragma unroll
        for (int o = 0; o < 4; o++)
            w[o] = *(const float4*)&sW[wb][jb + 8 * o][ro + ch * 4];
        #pragma unroll
        for (int ni = 0; ni < 4; ni++)
            #pragma unroll
            for (int o = 0; o < 4; o++) {
                acc[ni][o] = fmaf(v[ni].x, w[o].x, acc[ni][o]);
                acc[ni][o] = fmaf(v[ni].y, w[o].y, acc[ni][o]);
                acc[ni][o] = fmaf(v[ni].z, w[o].z, acc[ni][o]);
                acc[ni][o] = fmaf(v[ni].w, w[o].w, acc[ni][o]);
            }
    }

    float* zT = (float*)g_zT;
    #pragma unroll
    for (int ni = 0; ni < 4; ni++) {
        int n = nbase + ni;
        if (n < N_NODES) {
            #pragma unroll
            for (int o = 0; o < 4; o++)
                zT[n * 128 + q * 32 + jb + 8 * o] = acc[ni][o];
        }
    }
}

// ---------------- linear2: out = tanh(agg2P*invP + agg2N*invN + z_self@Wself + b) ----------------
#define KS2 36
__global__ void __launch_bounds__(256, 4)
linear2_lite(const float* __restrict__ w2b, const float* __restrict__ b2b,
             const float* __restrict__ w2u, const float* __restrict__ b2u,
             float* __restrict__ out)
{
    __shared__ float sW[2][32][KS2];   // self rows 64:95
    __shared__ float sB[64];
    int tid = threadIdx.x;
    for (int i = tid; i < 32 * 32; i += 256) {
        int k = i >> 5, j = i & 31;
        sW[0][j][k] = w2b[2048 + i];
        sW[1][j][k] = w2u[2048 + i];
    }
    if (tid < 32) { sB[tid] = b2b[tid]; sB[tid + 32] = b2u[tid]; }
    __syncthreads();

    int jg = tid & 15, ng = tid >> 4;
    int branch = jg >> 3, jb = jg & 7;
    int nbase = blockIdx.x * 64 + ng * 4;
    int nidx[4];
    #pragma unroll
    for (int ni = 0; ni < 4; ni++) {
        int n = nbase + ni; if (n > N_NODES - 1) n = N_NODES - 1;
        nidx[ni] = n;
    }

    const float* z = (const float*)g_z;
    float acc[4][4];
    #pragma unroll
    for (int ni = 0; ni < 4; ni++)
        #pragma unroll
        for (int o = 0; o < 4; o++)
            acc[ni][o] = sB[branch * 32 + jb + 8 * o];

    #pragma unroll
    for (int ch = 0; ch < 8; ch++) {
        float4 v[4], w[4];
        #pragma unroll
        for (int ni = 0; ni < 4; ni++)
            v[ni] = __ldg((const float4*)(z + nidx[ni] * 64 + branch * 32 + ch * 4));
        #pragma unroll
        for (int o = 0; o < 4; o++)
            w[o] = *(const float4*)&sW[branch][jb + 8 * o][ch * 4];
        #pragma unroll
        for (int ni = 0; ni < 4; ni++)
            #pragma unroll
            for (int o = 0; o < 4; o++) {
                acc[ni][o] = fmaf(v[ni].x, w[o].x, acc[ni][o]);
                acc[ni][o] = fmaf(v[ni].y, w[o].y, acc[ni][o]);
                acc[ni][o] = fmaf(v[ni].z, w[o].z, acc[ni][o]);
                acc[ni][o] = fmaf(v[ni].w, w[o].w, acc[ni][o]);
            }
    }

    const float* aU = (const float*)g_agg2P;
    const float* aV = (const float*)g_agg2N;
    #pragma unroll
    for (int ni = 0; ni < 4; ni++) {
        int n = nbase + ni;
        if (n < N_NODES) {
            float invP = 1.0f / fmaxf(g_cntP[n], 1.0f);
            float invN = 1.0f / fmaxf(g_cntN[n], 1.0f);
            #pragma unroll
            for (int o = 0; o < 4; o++) {
                int j = branch * 32 + jb + 8 * o;
                float au = __ldg(aU + n * 64 + j);
                float av = __ldg(aV + n * 64 + j);
                out[n * 64 + j] = ftanh(acc[ni][o] + au * invP + av * invN);
            }
        }
    }
}

// ---------------- launch ----------------
extern "C" void kernel_launch(void* const* d_in, const int* in_sizes, int n_in,
                              void* d_out, int out_size)
{
    const float* x    = (const float*)d_in[0];
    const int* posEI  = (const int*)d_in[1];
    const int* negEI  = (const int*)d_in[2];
    const float* w1b  = (const float*)d_in[3];
    const float* b1b  = (const float*)d_in[4];
    const float* w1u  = (const float*)d_in[5];
    const float* b1u  = (const float*)d_in[6];
    const float* w2b  = (const float*)d_in[7];
    const float* b2b  = (const float*)d_in[8];
    const float* w2u  = (const float*)d_in[9];
    const float* b2u  = (const float*)d_in[10];
    float* out = (float*)d_out;

    int E = in_sizes[1] / 2;             // 1,600,000
    const int* posSrc = posEI;
    const int* posDst = posEI + E;
    const int* negSrc = negEI;
    const int* negDst = negEI + E;

    int zero1Grid = (N_NODES * 8 + 255) / 256;
    int zero2Grid = (N_NODES * 16 + 255) / 256;
    int agg1Grid  = (E * 8 + 255) / 256;    // 50,000
    int agg2Grid  = (E * 16 + 255) / 256;   // 100,000
    int lin64Grid = (N_NODES + 63) / 64;    // 1563
    int lin32Grid = (N_NODES + 31) / 32;    // 3125

    // --- layer 1 ---
    zero1<<<zero1Grid, 256>>>();
    transform1_kernel<<<lin64Grid, 256>>>(x, w1b, w1u);
    agg_slice<<<agg1Grid, 256>>>(posSrc, posDst, E, 1, 0);
    agg_slice<<<agg1Grid, 256>>>(negSrc, negDst, E, 1, 1);
    linear1_lite<<<lin64Grid, 256>>>(x, w1b, b1b, w1u, b1u);

    // --- layer 2 ---
    zero2<<<zero2Grid, 256>>>();
    transform2_kernel<<<lin32Grid, 256>>>(w2b, w2u);
    agg_slice<<<agg2Grid, 256>>>(posSrc, posDst, E, 2, 0);
    agg_slice<<<agg2Grid, 256>>>(negSrc, negDst, E, 2, 1);
    linear2_lite<<<lin64Grid, 256>>>(w2b, b2b, w2u, b2u, out);
}